// round 14
// baseline (speedup 1.0000x reference)
#include <cuda_runtime.h>
#include <cstdint>

// Output: (256, 64, 48, 320) float32
// out[n][c][i][j] = x[box_img[n]][c][ y0+i*h/48 ][ x0+j*w/320 ]

#define H_IN   200
#define W_IN   320
#define C_IN   64
#define N_BOX  256
#define H_OUT  48
#define W_OUT  320

#define C_PASS 8                  // channels per pass
#define NPASS  (C_IN / C_PASS)    // 8
#define J4B    40                 // float4-pair slots (each thread: j4, j4+40)
#define NTHREADS (J4B * C_PASS)   // 320

__global__ __launch_bounds__(NTHREADS, 5)
void roi_crop_kernel(const float* __restrict__ x,
                     const int*  __restrict__ bboxes,
                     const int*  __restrict__ box_img,
                     float*      __restrict__ out)
{
    // One block per (n, i). blockIdx.x = n * H_OUT + i
    const int bi = blockIdx.x;
    const int i  = bi % H_OUT;
    const int n  = bi / H_OUT;

    const int tid  = threadIdx.x;
    const int j4   = tid % J4B;     // first float4 slot; second is j4+40
    const int csub = tid / J4B;     // 0..7, channel sub-slot

    // bbox math — once per thread, hoisted out of the channel loop
    int4 b = __ldg(reinterpret_cast<const int4*>(bboxes) + n);
    int x0 = min(max(b.x, 0), W_IN - 1);
    int y0 = min(max(b.y, 0), H_IN - 1);
    int x1 = min(max(b.z, 0), W_IN - 1);
    int y1 = min(max(b.w, 0), H_IN - 1);
    x1 = max(x1, x0);
    y1 = max(y1, y0);
    const int h = y1 - y0 + 1;
    const int w = x1 - x0 + 1;

    const int r   = y0 + (i * h) / H_OUT;
    const int img = __ldg(box_img + n);

    const int jA = j4 * 4;          // first float4 start column (output)
    const int jB = jA + 160;        // second float4 start column (j4+40)*4

    const int a0 = x0 + ((jA + 0) * w) / W_OUT;
    const int a1 = x0 + ((jA + 1) * w) / W_OUT;
    const int a2 = x0 + ((jA + 2) * w) / W_OUT;
    const int a3 = x0 + ((jA + 3) * w) / W_OUT;
    const int b0 = x0 + ((jB + 0) * w) / W_OUT;
    const int b1 = x0 + ((jB + 1) * w) / W_OUT;
    const int b2 = x0 + ((jB + 2) * w) / W_OUT;
    const int b3 = x0 + ((jB + 3) * w) / W_OUT;

    const float* src = x
        + ((size_t)img * C_IN + csub) * (size_t)(H_IN * W_IN)
        + (size_t)r * W_IN;
    float* dst = out
        + (((size_t)n * C_IN + csub) * H_OUT + i) * (size_t)W_OUT + jA;

    const size_t src_stride = (size_t)C_PASS * H_IN * W_IN;   // floats
    const size_t dst_stride = (size_t)C_PASS * H_OUT * W_OUT; // floats

    // Depth-1 software pipeline: next pass's 8 gathers in flight before the
    // current pass's two adjacent 512B-contiguous warp stores.
    float4 vA, vB;
    vA.x = __ldg(src + a0);  vA.y = __ldg(src + a1);
    vA.z = __ldg(src + a2);  vA.w = __ldg(src + a3);
    vB.x = __ldg(src + b0);  vB.y = __ldg(src + b1);
    vB.z = __ldg(src + b2);  vB.w = __ldg(src + b3);

    #pragma unroll
    for (int p = 0; p < NPASS - 1; ++p) {
        const float* nsrc = src + src_stride;
        float4 nA, nB;
        nA.x = __ldg(nsrc + a0);  nA.y = __ldg(nsrc + a1);
        nA.z = __ldg(nsrc + a2);  nA.w = __ldg(nsrc + a3);
        nB.x = __ldg(nsrc + b0);  nB.y = __ldg(nsrc + b1);
        nB.z = __ldg(nsrc + b2);  nB.w = __ldg(nsrc + b3);

        __stcs(reinterpret_cast<float4*>(dst), vA);        // evict-first
        __stcs(reinterpret_cast<float4*>(dst + 160), vB);  // adjacent 512B run

        vA = nA;  vB = nB;
        src = nsrc;
        dst += dst_stride;
    }
    __stcs(reinterpret_cast<float4*>(dst), vA);
    __stcs(reinterpret_cast<float4*>(dst + 160), vB);
}

extern "C" void kernel_launch(void* const* d_in, const int* in_sizes, int n_in,
                              void* d_out, int out_size)
{
    const float* x       = (const float*)d_in[0];
    const int*   bboxes  = (const int*)  d_in[1];
    const int*   box_img = (const int*)  d_in[2];
    float*       out     = (float*)      d_out;

    const int blocks = N_BOX * H_OUT;   // 12288
    roi_crop_kernel<<<blocks, NTHREADS>>>(x, bboxes, box_img, out);
}